// round 16
// baseline (speedup 1.0000x reference)
#include <cuda_runtime.h>
#include <cstdint>

// MultiHeadAttention_5128190951704 — algebraic collapse:
//   softmax rows sum to 1 and 'bnqk,bnvd->bnqd' is separable in k/v, so
//   y[b,o,d] = b_proj[o] + sum_n wp_sum[o,n] * sum_c wv_sum[n,c] * x[b,c,d]
// Rank-8 channel map per position. Memory floor: 256 MB => ~37 us.
//
// R15->R18: SMEM diet (reduction scratch overlays dead wv2 region) ->
// 68 KB -> 3 CTAs/SM (24 warps); launch_bounds(256,3) caps regs at 84;
// phase-1 unroll 4 to fit staging in the register budget.

#define B_   16
#define C_   512
#define NH_  8
#define S_   4096          // H*W
#define TPB  256
#define G_   4             // channel groups per block
#define GSZ  64            // threads per group
#define P_   256           // positions per block (4 per thread)
#define CPG  128           // channels per group

typedef unsigned long long ull;

// Folded weights (alloc-free rule: __device__ globals), f32x2-duplicated
__device__ ull g_wv2[C_ * NH_];   // [c][n]
__device__ ull g_wp2[C_ * NH_];   // [o][n]

__device__ __forceinline__ ull dup2(float v) {
    ull r;
    asm("mov.b64 %0, {%1, %1};" : "=l"(r) : "r"(__float_as_uint(v)));
    return r;
}
__device__ __forceinline__ ull fma2(ull a, ull b, ull c) {
    ull d;
    asm("fma.rn.f32x2 %0, %1, %2, %3;" : "=l"(d) : "l"(a), "l"(b), "l"(c));
    return d;
}
__device__ __forceinline__ ull add2(ull a, ull b) {
    ull d;
    asm("add.rn.f32x2 %0, %1, %2;" : "=l"(d) : "l"(a), "l"(b));
    return d;
}

// ---------------------------------------------------------------------------
// Prep: fold weights (8192 sums of 64 terms; ~2 MB reads, trivial cost).
// ---------------------------------------------------------------------------
__global__ void prep_kernel(const float* __restrict__ wqkv,
                            const float* __restrict__ wproj) {
    int t = blockIdx.x * blockDim.x + threadIdx.x;
    if (t < NH_ * C_) {
        // wv_sum[n][c] = sum_j wqkv[2C + n*64 + j][c], stored [c][n] dup'd
        int n = t >> 9, c = t & (C_ - 1);
        const float* p = wqkv + (size_t)(2 * C_ + n * 64) * C_ + c;
        float s = 0.f;
        #pragma unroll
        for (int j = 0; j < 64; j++) s += p[(size_t)j * C_];
        g_wv2[c * NH_ + n] = dup2(s);
    } else if (t < 2 * NH_ * C_) {
        // wp_sum[o][n] = sum_j wproj[o][n*64 + j], stored [o][n] dup'd
        int u = t - NH_ * C_;
        int o = u >> 3, n = u & 7;
        const float* p = wproj + (size_t)o * C_ + n * 64;
        float s = 0.f;
        #pragma unroll
        for (int j = 0; j < 64; j++) s += p[j];
        g_wp2[o * NH_ + n] = dup2(s);
    }
}

// ---------------------------------------------------------------------------
// Main kernel: 256 blocks x 256 threads, 3 CTAs/SM.
// Group g (64 threads): phase1 over channels [g*128, g*128+128) for the
// block's 256 positions (4/thread, LDG.128); reduction through the dead
// wv2 SMEM region (XOR-swizzled, conflict-free); phase2 over output
// channels [g*128, g*128+128) (STG.128).
// SMEM ulls: wv2/red 4096 | wp2 4096 | bias 512 -> 68 KB.
// ---------------------------------------------------------------------------
#define SMEM_ULLS  (2 * C_ * NH_ + C_)
#define SMEM_BYTES (SMEM_ULLS * 8)   // 69632 = 68 KB

__global__ void __launch_bounds__(TPB, 3)
attn_main(const float* __restrict__ x,
          const float* __restrict__ bias,
          float* __restrict__ y) {
    extern __shared__ ull smem[];
    ull* s_wv2 = smem;                       // [c][n] dup'd; dead after ph.1
    ull* s_wp2 = smem + C_ * NH_;            // [o][n] dup'd
    ull* s_b2  = smem + 2 * C_ * NH_;        // [o] dup'd
    ulonglong2* s_red = (ulonglong2*)smem;   // overlay: [thread][8 chunks]

    const int tid = threadIdx.x;
    for (int t = tid; t < C_ * NH_; t += TPB) {
        s_wv2[t] = g_wv2[t];
        s_wp2[t] = g_wp2[t];
    }
    for (int t = tid; t < C_; t += TPB) s_b2[t] = dup2(bias[t]);
    __syncthreads();

    const int b    = blockIdx.x >> 4;        // 16 batches
    const int tile = blockIdx.x & 15;        // 16 tiles of 256 positions
    const int g    = tid >> 6;               // channel/output group
    const int tg   = tid & (GSZ - 1);        // position-quad owner
    const int qoff = tile * (P_ / 4) + tg;   // quad index within row

    // ---- Phase 1: partial acc over this group's 128 channels ----
    const ulonglong2* xp = (const ulonglong2*)x
        + (size_t)(b * C_ + g * CPG) * (S_ / 4) + qoff;
    ull a0[NH_], a1[NH_];                    // positions {0,1} and {2,3}
    #pragma unroll
    for (int n = 0; n < NH_; n++) { a0[n] = 0ull; a1[n] = 0ull; }

    #pragma unroll 4
    for (int cc = 0; cc < CPG; cc++) {
        ulonglong2 xv = xp[(size_t)cc * (S_ / 4)];   // LDG.128, coalesced
        const ulonglong2* wv =
            (const ulonglong2*)(s_wv2 + (g * CPG + cc) * NH_);
        ulonglong2 w0 = wv[0], w1 = wv[1], w2 = wv[2], w3 = wv[3];
        a0[0] = fma2(w0.x, xv.x, a0[0]);  a1[0] = fma2(w0.x, xv.y, a1[0]);
        a0[1] = fma2(w0.y, xv.x, a0[1]);  a1[1] = fma2(w0.y, xv.y, a1[1]);
        a0[2] = fma2(w1.x, xv.x, a0[2]);  a1[2] = fma2(w1.x, xv.y, a1[2]);
        a0[3] = fma2(w1.y, xv.x, a0[3]);  a1[3] = fma2(w1.y, xv.y, a1[3]);
        a0[4] = fma2(w2.x, xv.x, a0[4]);  a1[4] = fma2(w2.x, xv.y, a1[4]);
        a0[5] = fma2(w2.y, xv.x, a0[5]);  a1[5] = fma2(w2.y, xv.y, a1[5]);
        a0[6] = fma2(w3.x, xv.x, a0[6]);  a1[6] = fma2(w3.x, xv.y, a1[6]);
        a0[7] = fma2(w3.y, xv.x, a0[7]);  a1[7] = fma2(w3.y, xv.y, a1[7]);
    }

    // ---- Cross-group reduction through the (dead) wv2 region ----
    __syncthreads();                         // everyone done reading wv2
    {
        // 8 chunks of 16B per thread, XOR-swizzled: conflict-free STS.128
        ulonglong2* r = s_red + tid * 8;
        const int sw = tid & 7;
        #pragma unroll
        for (int h = 0; h < 4; h++) {
            r[h ^ sw]       = make_ulonglong2(a0[2 * h], a0[2 * h + 1]);
            r[(h + 4) ^ sw] = make_ulonglong2(a1[2 * h], a1[2 * h + 1]);
        }
    }
    __syncthreads();

    ull t0[NH_], t1[NH_];
    #pragma unroll
    for (int n = 0; n < NH_; n++) { t0[n] = 0ull; t1[n] = 0ull; }
    {
        const int sw = tg & 7;               // (gg*64+tg)&7 == tg&7
        #pragma unroll
        for (int gg = 0; gg < G_; gg++) {
            const ulonglong2* r = s_red + (gg * GSZ + tg) * 8;
            #pragma unroll
            for (int h = 0; h < 4; h++) {
                ulonglong2 v0 = r[h ^ sw];
                ulonglong2 v1 = r[(h + 4) ^ sw];
                t0[2 * h]     = add2(t0[2 * h],     v0.x);
                t0[2 * h + 1] = add2(t0[2 * h + 1], v0.y);
                t1[2 * h]     = add2(t1[2 * h],     v1.x);
                t1[2 * h + 1] = add2(t1[2 * h + 1], v1.y);
            }
        }
    }

    // ---- Phase 2: this group's 128 output channels, STG.128 ----
    ulonglong2* yp = (ulonglong2*)y
        + (size_t)(b * C_ + g * CPG) * (S_ / 4) + qoff;
    #pragma unroll 4
    for (int oo = 0; oo < CPG; oo++) {
        const int o = g * CPG + oo;
        const ulonglong2* wp = (const ulonglong2*)(s_wp2 + o * NH_);
        ulonglong2 w0 = wp[0], w1 = wp[1], w2 = wp[2], w3 = wp[3];
        ull bb = s_b2[o];
        ull r0 = bb, r1 = bb;
        r0 = fma2(w0.x, t0[0], r0);  r1 = fma2(w0.x, t1[0], r1);
        r0 = fma2(w0.y, t0[1], r0);  r1 = fma2(w0.y, t1[1], r1);
        r0 = fma2(w1.x, t0[2], r0);  r1 = fma2(w1.x, t1[2], r1);
        r0 = fma2(w1.y, t0[3], r0);  r1 = fma2(w1.y, t1[3], r1);
        r0 = fma2(w2.x, t0[4], r0);  r1 = fma2(w2.x, t1[4], r1);
        r0 = fma2(w2.y, t0[5], r0);  r1 = fma2(w2.y, t1[5], r1);
        r0 = fma2(w3.x, t0[6], r0);  r1 = fma2(w3.x, t1[6], r1);
        r0 = fma2(w3.y, t0[7], r0);  r1 = fma2(w3.y, t1[7], r1);
        yp[(size_t)oo * (S_ / 4)] = make_ulonglong2(r0, r1);  // STG.128
    }
}

// ---------------------------------------------------------------------------
extern "C" void kernel_launch(void* const* d_in, const int* in_sizes, int n_in,
                              void* d_out, int out_size) {
    const float* x     = (const float*)d_in[0];
    const float* wqkv  = (const float*)d_in[1];
    const float* wproj = (const float*)d_in[2];
    const float* bproj = (const float*)d_in[3];
    float* y = (float*)d_out;

    cudaFuncSetAttribute(attn_main, cudaFuncAttributeMaxDynamicSharedMemorySize,
                         SMEM_BYTES);

    prep_kernel<<<32, 256>>>(wqkv, wproj);
    attn_main<<<B_ * (S_ / P_), TPB, SMEM_BYTES>>>(x, bproj, y);
}

// round 17
// speedup vs baseline: 1.0156x; 1.0156x over previous
#include <cuda_runtime.h>
#include <cstdint>

// MultiHeadAttention_5128190951704 — algebraic collapse:
//   softmax rows sum to 1 and 'bnqk,bnvd->bnqd' is separable in k/v, so
//   y[b,o,d] = b_proj[o] + sum_n wp_sum[o,n] * sum_c wv_sum[n,c] * x[b,c,d]
// Rank-8 channel map per position. Memory floor: 256 MB => ~37 us.
//
// R15->R18: SMEM diet (reduction scratch overlays dead wv2 region) ->
// 68 KB -> 3 CTAs/SM (24 warps); launch_bounds(256,3) caps regs at 84;
// phase-1 unroll 4 to fit staging in the register budget.

#define B_   16
#define C_   512
#define NH_  8
#define S_   4096          // H*W
#define TPB  256
#define G_   4             // channel groups per block
#define GSZ  64            // threads per group
#define P_   256           // positions per block (4 per thread)
#define CPG  128           // channels per group

typedef unsigned long long ull;

// Folded weights (alloc-free rule: __device__ globals), f32x2-duplicated
__device__ ull g_wv2[C_ * NH_];   // [c][n]
__device__ ull g_wp2[C_ * NH_];   // [o][n]

__device__ __forceinline__ ull dup2(float v) {
    ull r;
    asm("mov.b64 %0, {%1, %1};" : "=l"(r) : "r"(__float_as_uint(v)));
    return r;
}
__device__ __forceinline__ ull fma2(ull a, ull b, ull c) {
    ull d;
    asm("fma.rn.f32x2 %0, %1, %2, %3;" : "=l"(d) : "l"(a), "l"(b), "l"(c));
    return d;
}
__device__ __forceinline__ ull add2(ull a, ull b) {
    ull d;
    asm("add.rn.f32x2 %0, %1, %2;" : "=l"(d) : "l"(a), "l"(b));
    return d;
}

// ---------------------------------------------------------------------------
// Prep: fold weights (8192 sums of 64 terms; ~2 MB reads, trivial cost).
// ---------------------------------------------------------------------------
__global__ void prep_kernel(const float* __restrict__ wqkv,
                            const float* __restrict__ wproj) {
    int t = blockIdx.x * blockDim.x + threadIdx.x;
    if (t < NH_ * C_) {
        // wv_sum[n][c] = sum_j wqkv[2C + n*64 + j][c], stored [c][n] dup'd
        int n = t >> 9, c = t & (C_ - 1);
        const float* p = wqkv + (size_t)(2 * C_ + n * 64) * C_ + c;
        float s = 0.f;
        #pragma unroll
        for (int j = 0; j < 64; j++) s += p[(size_t)j * C_];
        g_wv2[c * NH_ + n] = dup2(s);
    } else if (t < 2 * NH_ * C_) {
        // wp_sum[o][n] = sum_j wproj[o][n*64 + j], stored [o][n] dup'd
        int u = t - NH_ * C_;
        int o = u >> 3, n = u & 7;
        const float* p = wproj + (size_t)o * C_ + n * 64;
        float s = 0.f;
        #pragma unroll
        for (int j = 0; j < 64; j++) s += p[j];
        g_wp2[o * NH_ + n] = dup2(s);
    }
}

// ---------------------------------------------------------------------------
// Main kernel: 256 blocks x 256 threads, 3 CTAs/SM.
// Group g (64 threads): phase1 over channels [g*128, g*128+128) for the
// block's 256 positions (4/thread, LDG.128); reduction through the dead
// wv2 SMEM region (XOR-swizzled, conflict-free); phase2 over output
// channels [g*128, g*128+128) (STG.128).
// SMEM ulls: wv2/red 4096 | wp2 4096 | bias 512 -> 68 KB.
// ---------------------------------------------------------------------------
#define SMEM_ULLS  (2 * C_ * NH_ + C_)
#define SMEM_BYTES (SMEM_ULLS * 8)   // 69632 = 68 KB

__global__ void __launch_bounds__(TPB, 3)
attn_main(const float* __restrict__ x,
          const float* __restrict__ bias,
          float* __restrict__ y) {
    extern __shared__ ull smem[];
    ull* s_wv2 = smem;                       // [c][n] dup'd; dead after ph.1
    ull* s_wp2 = smem + C_ * NH_;            // [o][n] dup'd
    ull* s_b2  = smem + 2 * C_ * NH_;        // [o] dup'd
    ulonglong2* s_red = (ulonglong2*)smem;   // overlay: [thread][8 chunks]

    const int tid = threadIdx.x;
    for (int t = tid; t < C_ * NH_; t += TPB) {
        s_wv2[t] = g_wv2[t];
        s_wp2[t] = g_wp2[t];
    }
    for (int t = tid; t < C_; t += TPB) s_b2[t] = dup2(bias[t]);
    __syncthreads();

    const int b    = blockIdx.x >> 4;        // 16 batches
    const int tile = blockIdx.x & 15;        // 16 tiles of 256 positions
    const int g    = tid >> 6;               // channel/output group
    const int tg   = tid & (GSZ - 1);        // position-quad owner
    const int qoff = tile * (P_ / 4) + tg;   // quad index within row

    // ---- Phase 1: partial acc over this group's 128 channels ----
    const ulonglong2* xp = (const ulonglong2*)x
        + (size_t)(b * C_ + g * CPG) * (S_ / 4) + qoff;
    ull a0[NH_], a1[NH_];                    // positions {0,1} and {2,3}
    #pragma unroll
    for (int n = 0; n < NH_; n++) { a0[n] = 0ull; a1[n] = 0ull; }

    #pragma unroll 4
    for (int cc = 0; cc < CPG; cc++) {
        ulonglong2 xv = xp[(size_t)cc * (S_ / 4)];   // LDG.128, coalesced
        const ulonglong2* wv =
            (const ulonglong2*)(s_wv2 + (g * CPG + cc) * NH_);
        ulonglong2 w0 = wv[0], w1 = wv[1], w2 = wv[2], w3 = wv[3];
        a0[0] = fma2(w0.x, xv.x, a0[0]);  a1[0] = fma2(w0.x, xv.y, a1[0]);
        a0[1] = fma2(w0.y, xv.x, a0[1]);  a1[1] = fma2(w0.y, xv.y, a1[1]);
        a0[2] = fma2(w1.x, xv.x, a0[2]);  a1[2] = fma2(w1.x, xv.y, a1[2]);
        a0[3] = fma2(w1.y, xv.x, a0[3]);  a1[3] = fma2(w1.y, xv.y, a1[3]);
        a0[4] = fma2(w2.x, xv.x, a0[4]);  a1[4] = fma2(w2.x, xv.y, a1[4]);
        a0[5] = fma2(w2.y, xv.x, a0[5]);  a1[5] = fma2(w2.y, xv.y, a1[5]);
        a0[6] = fma2(w3.x, xv.x, a0[6]);  a1[6] = fma2(w3.x, xv.y, a1[6]);
        a0[7] = fma2(w3.y, xv.x, a0[7]);  a1[7] = fma2(w3.y, xv.y, a1[7]);
    }

    // ---- Cross-group reduction through the (dead) wv2 region ----
    __syncthreads();                         // everyone done reading wv2
    {
        // 8 chunks of 16B per thread, XOR-swizzled: conflict-free STS.128
        ulonglong2* r = s_red + tid * 8;
        const int sw = tid & 7;
        #pragma unroll
        for (int h = 0; h < 4; h++) {
            r[h ^ sw]       = make_ulonglong2(a0[2 * h], a0[2 * h + 1]);
            r[(h + 4) ^ sw] = make_ulonglong2(a1[2 * h], a1[2 * h + 1]);
        }
    }
    __syncthreads();

    ull t0[NH_], t1[NH_];
    #pragma unroll
    for (int n = 0; n < NH_; n++) { t0[n] = 0ull; t1[n] = 0ull; }
    {
        const int sw = tg & 7;               // (gg*64+tg)&7 == tg&7
        #pragma unroll
        for (int gg = 0; gg < G_; gg++) {
            const ulonglong2* r = s_red + (gg * GSZ + tg) * 8;
            #pragma unroll
            for (int h = 0; h < 4; h++) {
                ulonglong2 v0 = r[h ^ sw];
                ulonglong2 v1 = r[(h + 4) ^ sw];
                t0[2 * h]     = add2(t0[2 * h],     v0.x);
                t0[2 * h + 1] = add2(t0[2 * h + 1], v0.y);
                t1[2 * h]     = add2(t1[2 * h],     v1.x);
                t1[2 * h + 1] = add2(t1[2 * h + 1], v1.y);
            }
        }
    }

    // ---- Phase 2: this group's 128 output channels, STG.128 ----
    ulonglong2* yp = (ulonglong2*)y
        + (size_t)(b * C_ + g * CPG) * (S_ / 4) + qoff;
    #pragma unroll 4
    for (int oo = 0; oo < CPG; oo++) {
        const int o = g * CPG + oo;
        const ulonglong2* wp = (const ulonglong2*)(s_wp2 + o * NH_);
        ulonglong2 w0 = wp[0], w1 = wp[1], w2 = wp[2], w3 = wp[3];
        ull bb = s_b2[o];
        ull r0 = bb, r1 = bb;
        r0 = fma2(w0.x, t0[0], r0);  r1 = fma2(w0.x, t1[0], r1);
        r0 = fma2(w0.y, t0[1], r0);  r1 = fma2(w0.y, t1[1], r1);
        r0 = fma2(w1.x, t0[2], r0);  r1 = fma2(w1.x, t1[2], r1);
        r0 = fma2(w1.y, t0[3], r0);  r1 = fma2(w1.y, t1[3], r1);
        r0 = fma2(w2.x, t0[4], r0);  r1 = fma2(w2.x, t1[4], r1);
        r0 = fma2(w2.y, t0[5], r0);  r1 = fma2(w2.y, t1[5], r1);
        r0 = fma2(w3.x, t0[6], r0);  r1 = fma2(w3.x, t1[6], r1);
        r0 = fma2(w3.y, t0[7], r0);  r1 = fma2(w3.y, t1[7], r1);
        yp[(size_t)oo * (S_ / 4)] = make_ulonglong2(r0, r1);  // STG.128
    }
}

// ---------------------------------------------------------------------------
extern "C" void kernel_launch(void* const* d_in, const int* in_sizes, int n_in,
                              void* d_out, int out_size) {
    const float* x     = (const float*)d_in[0];
    const float* wqkv  = (const float*)d_in[1];
    const float* wproj = (const float*)d_in[2];
    const float* bproj = (const float*)d_in[3];
    float* y = (float*)d_out;

    cudaFuncSetAttribute(attn_main, cudaFuncAttributeMaxDynamicSharedMemorySize,
                         SMEM_BYTES);

    prep_kernel<<<32, 256>>>(wqkv, wproj);
    attn_main<<<B_ * (S_ / P_), TPB, SMEM_BYTES>>>(x, bproj, y);
}